// round 6
// baseline (speedup 1.0000x reference)
#include <cuda_runtime.h>
#include <cstdint>

// Problem constants
#define B_TOT 4096
#define DIN   2048
#define DOUT  2048
// per core: G[r=8][o=512][x=512][s=8], offset = r*2097152 + o*4096 + x*8 + s

// Scratch (static device globals — no allocation)
__device__ float g_Ghat[4][8][4096];     // [core][r][x*8+s]  512 KB
__device__ float g_S[4][B_TOT][64];      // [core][b][r*8+s]  4 MB
__device__ float g_env[4][B_TOT][64];    // [core][b][r*8+s]  4 MB

// ---------------------------------------------------------------------------
// Kernel 1: Ghat[core][r][p] = sum_o G[core][r][o][p]   (p = x*8+s in 0..4095)
// grid 512 = 4 cores * 8 r * 16 chunks, block 256. Coalesced 128B per o-step.
// ---------------------------------------------------------------------------
__global__ void k_ghat(const float* __restrict__ c0, const float* __restrict__ c1,
                       const float* __restrict__ c2, const float* __restrict__ c3)
{
    int bid   = blockIdx.x;
    int chunk = bid & 15;
    int r     = (bid >> 4) & 7;
    int core  = bid >> 7;
    const float* G = (core == 0) ? c0 : (core == 1) ? c1 : (core == 2) ? c2 : c3;
    int p = chunk * 256 + threadIdx.x;
    const float* base = G + (size_t)r * 2097152 + p;
    float acc = 0.f;
#pragma unroll 8
    for (int o = 0; o < 512; o++) acc += base[(size_t)o * 4096];
    g_Ghat[core][r][p] = acc;
}

// ---------------------------------------------------------------------------
// Kernel 2: S[core][b][r,s] = sum_x Ghat[core][r][x,s] * X[b][core*512+x]
// block = 256 threads = (4 cores x 64 rs), 4 batches per block, grid 1024.
// ---------------------------------------------------------------------------
__global__ void k_S(const float* __restrict__ X)
{
    __shared__ float xs[4][DIN];   // 32 KB
    int t  = threadIdx.x;
    int b0 = blockIdx.x * 4;
#pragma unroll
    for (int it = 0; it < 32; it++) {             // 4*2048/256 = 32
        int i = t + it * 256;
        xs[i >> 11][i & 2047] = X[(size_t)(b0 + (i >> 11)) * DIN + (i & 2047)];
    }
    __syncthreads();

    int core = t >> 6, rs = t & 63, r = rs >> 3, s = rs & 7;
    const float* gh = g_Ghat[core][r];
    const int xo = core * 512;
    float a0 = 0.f, a1 = 0.f, a2 = 0.f, a3 = 0.f;
#pragma unroll 8
    for (int x = 0; x < 512; x++) {
        float ghv = gh[x * 8 + s];
        a0 += ghv * xs[0][xo + x];
        a1 += ghv * xs[1][xo + x];
        a2 += ghv * xs[2][xo + x];
        a3 += ghv * xs[3][xo + x];
    }
    g_S[core][b0 + 0][rs] = a0;
    g_S[core][b0 + 1][rs] = a1;
    g_S[core][b0 + 2][rs] = a2;
    g_S[core][b0 + 3][rs] = a3;
}

// ---------------------------------------------------------------------------
// Kernel 3: chains + env. P1=S0, P2=S0@S1, P3=P2@S2; Q2=S3, Q1=S2@S3, Q0=S1@Q1
// env_i[r,s] = sum_p Q_i[s,p] P_i[p,r]  (P0=I, Q3=I)
// block 256 = 4 batches x 64 (r,s) threads. grid 1024.
// ---------------------------------------------------------------------------
__global__ void k_chain()
{
    __shared__ float Sm[4][4][64];                 // [bsub][core][r*8+s]
    __shared__ float P2s[4][64], P3s[4][64], Q1s[4][64], Q0s[4][64];
    int t = threadIdx.x;
    int bsub = t >> 6, rs = t & 63, r = rs >> 3, s = rs & 7;
    int b = blockIdx.x * 4 + bsub;

#pragma unroll
    for (int c = 0; c < 4; c++) Sm[bsub][c][rs] = g_S[c][b][rs];
    __syncthreads();

    float p2 = 0.f, q1 = 0.f;
#pragma unroll
    for (int p = 0; p < 8; p++) {
        p2 += Sm[bsub][0][r * 8 + p] * Sm[bsub][1][p * 8 + s];   // S0@S1
        q1 += Sm[bsub][2][r * 8 + p] * Sm[bsub][3][p * 8 + s];   // S2@S3
    }
    P2s[bsub][rs] = p2; Q1s[bsub][rs] = q1;
    __syncthreads();

    float p3 = 0.f, q0 = 0.f;
#pragma unroll
    for (int p = 0; p < 8; p++) {
        p3 += P2s[bsub][r * 8 + p] * Sm[bsub][2][p * 8 + s];     // P2@S2
        q0 += Sm[bsub][1][r * 8 + p] * Q1s[bsub][p * 8 + s];     // S1@Q1
    }
    P3s[bsub][rs] = p3; Q0s[bsub][rs] = q0;
    __syncthreads();

    float e1 = 0.f, e2 = 0.f;
#pragma unroll
    for (int p = 0; p < 8; p++) {
        e1 += Q1s[bsub][s * 8 + p] * Sm[bsub][0][p * 8 + r];     // Q1@P1(=S0)
        e2 += Sm[bsub][3][s * 8 + p] * P2s[bsub][p * 8 + r];     // Q2(=S3)@P2
    }
    g_env[0][b][rs] = Q0s[bsub][s * 8 + r];   // Q0^T
    g_env[1][b][rs] = e1;
    g_env[2][b][rs] = e2;
    g_env[3][b][rs] = P3s[bsub][s * 8 + r];   // P3^T
}

// ---------------------------------------------------------------------------
// Kernel 4: out[b, core*512+o] = sum_r sum_{x,s} (env[b,r8+s]*x[b,x]) * G[r,o,x,s]
// tf32 mma.sync m16n8k8: k8 == s-dim exactly. CTA tile 128(M) x 64(N), 8 warps
// as 4(M)x2(N), warp tile 32x32 (2 m-frags x 4 n-frags).
// ---------------------------------------------------------------------------
__device__ __forceinline__ uint32_t f2tf32(float f)
{
    uint32_t u;
    asm("cvt.rna.tf32.f32 %0, %1;" : "=r"(u) : "f"(f));
    return u;
}

__device__ __forceinline__ void mma8(float* d, const uint32_t* a, const uint32_t* b)
{
    asm volatile(
        "mma.sync.aligned.m16n8k8.row.col.f32.tf32.tf32.f32 "
        "{%0,%1,%2,%3}, {%4,%5,%6,%7}, {%8,%9}, {%0,%1,%2,%3};\n"
        : "+f"(d[0]), "+f"(d[1]), "+f"(d[2]), "+f"(d[3])
        : "r"(a[0]), "r"(a[1]), "r"(a[2]), "r"(a[3]), "r"(b[0]), "r"(b[1]));
}

#define ENV_LD 65
#define X_LD   17
#define B_LD   132
#define SMEM_FLOATS (128 * ENV_LD + 128 * X_LD + 64 * B_LD)
#define SMEM_BYTES  (SMEM_FLOATS * 4)

__global__ void __launch_bounds__(256, 2) k_gemm(
    const float* __restrict__ X,
    const float* __restrict__ c0, const float* __restrict__ c1,
    const float* __restrict__ c2, const float* __restrict__ c3,
    const float* __restrict__ bias, float* __restrict__ out)
{
    extern __shared__ float sm[];
    float* s_env = sm;                       // [128][65]
    float* s_x   = sm + 128 * ENV_LD;        // [128][17]  (16 x-values per chunk)
    float* s_B   = s_x + 128 * X_LD;         // [64][132]  (128 k per stage, tf32)

    const int core = blockIdx.z;
    const float* G = (core == 0) ? c0 : (core == 1) ? c1 : (core == 2) ? c2 : c3;
    const int m0 = blockIdx.y * 128;
    const int n0 = blockIdx.x * 64;

    const int tid  = threadIdx.x;
    const int lane = tid & 31, warp = tid >> 5;
    const int wm = warp & 3, wn = warp >> 2;         // 4 m-warps x 2 n-warps
    const int g = lane >> 2, tg = lane & 3;
    const int row0 = wm * 32 + g;                    // warp-local base row (+8,+16,+24)

    // Stage env tile [128][64] once
#pragma unroll
    for (int it = 0; it < 32; it++) {
        int i = tid + it * 256;
        int rr = i >> 6, cc = i & 63;
        s_env[rr * ENV_LD + cc] = g_env[core][m0 + rr][cc];
    }

    float acc[2][4][4];
#pragma unroll
    for (int mf = 0; mf < 2; mf++)
#pragma unroll
        for (int nf = 0; nf < 4; nf++)
#pragma unroll
            for (int q = 0; q < 4; q++) acc[mf][nf][q] = 0.f;

    for (int xc = 0; xc < 32; xc++) {                 // 16 x-values per chunk
        __syncthreads();                              // protect s_x reuse
#pragma unroll
        for (int it = 0; it < 8; it++) {              // 128*16/256
            int i = tid + it * 256;
            int rr = i >> 4, j = i & 15;
            s_x[rr * X_LD + j] = X[(size_t)(m0 + rr) * DIN + core * 512 + xc * 16 + j];
        }
        for (int r = 0; r < 8; r++) {
            __syncthreads();                          // protect s_B reuse (+s_x ready @r=0)
            // stage B: 64 o-rows x 128 k, convert to tf32
            const float* Gp = G + (size_t)r * 2097152 + (size_t)n0 * 4096 + xc * 128;
#pragma unroll
            for (int it = 0; it < 8; it++) {          // 2048 float4 / 256
                int i = tid + it * 256;
                int o = i >> 5, k4 = (i & 31) << 2;
                float4 v = *(const float4*)(Gp + (size_t)o * 4096 + k4);
                float* dst = s_B + o * B_LD + k4;
                dst[0] = __uint_as_float(f2tf32(v.x));
                dst[1] = __uint_as_float(f2tf32(v.y));
                dst[2] = __uint_as_float(f2tf32(v.z));
                dst[3] = __uint_as_float(f2tf32(v.w));
            }
            __syncthreads();

            // env fragments for this r (constant over x): A[row][s] layout,
            // a0:(g,tg) a1:(g+8,tg) a2:(g,tg+4) a3:(g+8,tg+4)
            float e[2][4];
#pragma unroll
            for (int mf = 0; mf < 2; mf++) {
                int rw = row0 + mf * 16;
                e[mf][0] = s_env[rw * ENV_LD + r * 8 + tg];
                e[mf][1] = s_env[(rw + 8) * ENV_LD + r * 8 + tg];
                e[mf][2] = s_env[rw * ENV_LD + r * 8 + tg + 4];
                e[mf][3] = s_env[(rw + 8) * ENV_LD + r * 8 + tg + 4];
            }

#pragma unroll
            for (int xs = 0; xs < 16; xs++) {
                uint32_t bf[4][2];
#pragma unroll
                for (int nf = 0; nf < 4; nf++) {
                    int o = wn * 32 + nf * 8 + g;     // b0:(k=tg,n=g) b1:(k=tg+4,n=g)
                    bf[nf][0] = __float_as_uint(s_B[o * B_LD + xs * 8 + tg]);
                    bf[nf][1] = __float_as_uint(s_B[o * B_LD + xs * 8 + tg + 4]);
                }
                uint32_t af[2][4];
#pragma unroll
                for (int mf = 0; mf < 2; mf++) {
                    int rw = row0 + mf * 16;
                    float xv0 = s_x[rw * X_LD + xs];
                    float xv1 = s_x[(rw + 8) * X_LD + xs];
                    af[mf][0] = f2tf32(e[mf][0] * xv0);
                    af[mf][1] = f2tf32(e[mf][1] * xv1);
                    af[mf][2] = f2tf32(e[mf][2] * xv0);
                    af[mf][3] = f2tf32(e[mf][3] * xv1);
                }
#pragma unroll
                for (int mf = 0; mf < 2; mf++)
#pragma unroll
                    for (int nf = 0; nf < 4; nf++)
                        mma8(acc[mf][nf], af[mf], bf[nf]);
            }
        }
    }

    // Epilogue: c0:(g,2tg) c1:(g,2tg+1) c2:(g+8,2tg) c3:(g+8,2tg+1)
#pragma unroll
    for (int mf = 0; mf < 2; mf++) {
        int row = m0 + row0 + mf * 16;
#pragma unroll
        for (int nf = 0; nf < 4; nf++) {
            int col = core * 512 + n0 + wn * 32 + nf * 8 + 2 * tg;
            out[(size_t)row * DOUT + col]           = acc[mf][nf][0] + bias[col];
            out[(size_t)row * DOUT + col + 1]       = acc[mf][nf][1] + bias[col + 1];
            out[(size_t)(row + 8) * DOUT + col]     = acc[mf][nf][2] + bias[col];
            out[(size_t)(row + 8) * DOUT + col + 1] = acc[mf][nf][3] + bias[col + 1];
        }
    }
}

// ---------------------------------------------------------------------------
extern "C" void kernel_launch(void* const* d_in, const int* in_sizes, int n_in,
                              void* d_out, int out_size)
{
    const float* X    = (const float*)d_in[0];
    const float* c0   = (const float*)d_in[1];
    const float* c1   = (const float*)d_in[2];
    const float* c2   = (const float*)d_in[3];
    const float* c3   = (const float*)d_in[4];
    const float* bias = (const float*)d_in[5];
    float* out = (float*)d_out;

    k_ghat<<<512, 256>>>(c0, c1, c2, c3);
    k_S<<<1024, 256>>>(X);
    k_chain<<<1024, 256>>>();

    cudaFuncSetAttribute(k_gemm, cudaFuncAttributeMaxDynamicSharedMemorySize, SMEM_BYTES);
    dim3 grid(8, 32, 4);   // N-tiles x M-tiles x cores
    k_gemm<<<grid, 256, SMEM_BYTES>>>(X, c0, c1, c2, c3, bias, out);
}